// round 15
// baseline (speedup 1.0000x reference)
#include <cuda_runtime.h>

#define B_   2
#define N_   169
#define NN_  338
#define C_   256
#define H_   4
#define HC_  1024
#define L_   3

typedef unsigned long long ull;

// ---------------- scratch (device globals) ---------------------------------
__device__ float g_x[NN_ * C_];               // running node features
__device__ float g_xl[NN_ * HC_];             // x @ Wl + bl
__device__ float g_xr[NN_ * HC_];             // x @ Wr + br
__device__ float g_agg[B_ * H_ * N_ * C_];    // per-head aggregation partials
__device__ float g_h[NN_ * C_];               // post layernorm
__device__ float g_m[NN_ * 2 * C_];           // mlp hidden

// ---------------- cp.async helpers ------------------------------------------
__device__ __forceinline__ unsigned s2u(const void* p)
{
    return (unsigned)__cvta_generic_to_shared(p);
}
__device__ __forceinline__ void cp16(unsigned dst, const void* src, bool ok)
{
    int sz = ok ? 16 : 0;
    asm volatile("cp.async.cg.shared.global [%0], [%1], 16, %2;"
                 :: "r"(dst), "l"(src), "r"(sz));
}
__device__ __forceinline__ void cp_commit()
{
    asm volatile("cp.async.commit_group;");
}
__device__ __forceinline__ void cp_wait0()
{
    asm volatile("cp.async.wait_group 0;" ::: "memory");
}

// ---------------- fused logits + softmax + aggregation + u/w ----------------
// grid (43 d-tiles, 8 bh), block 128 = 4 warps.
// u_s=<att,xl_s> and w_d=<att,xr_d> computed in-kernel from staged tiles
// (uw_kernel eliminated). logit = 0.6(u_s+w_d) + 0.4 sum att|xl+xr|.
struct AttnSmem {
    union {
        struct {
            float XLs[2][6][32][36];
            float XR[4][256];
            float A4[256];
        } pa;
        struct {
            float Xs[2][32][260];
        } pb;
    } u;
    float AL[4][193];
    float MX[4][2];
    float SS[4][2];
};
#define ATTN_SMEM_BYTES sizeof(AttnSmem)

__global__ __launch_bounds__(128) void attn_agg_kernel(const float* __restrict__ xl,
                                                       const float* __restrict__ xr,
                                                       const float* __restrict__ att_l,
                                                       float* __restrict__ agg)
{
    extern __shared__ __align__(16) char smem_raw[];
    AttnSmem* sm = (AttnSmem*)smem_raw;

    int tid = threadIdx.x;
    int lane = tid & 31;
    int wid = tid >> 5;
    int ty = wid >> 1;            // d-pair 0..1
    int hf = wid & 1;             // s-half: bands {0,1,2} or {3,4,5}
    int dt = blockIdx.x, bh = blockIdx.y;
    int b = bh >> 2, h = bh & 3;
    int d0 = dt * 4 + ty * 2;
    int d1 = d0 + 1;
    bool dok0 = d0 < N_, dok1 = d1 < N_;

    const float* xlh = xl + (size_t)b * N_ * HC_ + h * C_;

    // ---- stage chunk 0 of XLs (cp16), then XR + A4 (sync LDG, once) ----
#pragma unroll
    for (int i = 0; i < 12; i++) {
        int f = tid + 128 * i;          // 1536 float4 total
        int st = f >> 8;
        int rem = f & 255;
        int row = rem >> 3;
        int c4 = rem & 7;
        int s = st * 32 + row;
        bool ok = s < N_;
        cp16(s2u(&sm->u.pa.XLs[0][st][row][c4 * 4]),
             &xlh[(size_t)(ok ? s : 0) * HC_ + c4 * 4], ok);
    }
    cp_commit();
#pragma unroll
    for (int i = 0; i < 4; i++) {
        int f = tid + 128 * i;          // 512 float2 for XR[4][256]
        int row = f >> 7;
        int cc = (f & 127) * 2;
        int dr = dt * 4 + row;
        float2 v = make_float2(0.f, 0.f);
        if (dr < N_) v = *(const float2*)&xr[(size_t)(b * N_ + dr) * HC_ + h * C_ + cc];
        *(float2*)&sm->u.pa.XR[row][cc] = v;
    }
    {
        float2 a = *(const float2*)&att_l[h * C_ + tid * 2];
        sm->u.pa.A4[tid * 2]     = 0.4f * a.x;
        sm->u.pa.A4[tid * 2 + 1] = 0.4f * a.y;
    }

    ull acc0[3], acc1[3], uacc[3];
    ull wacc0 = 0ull, wacc1 = 0ull;
#pragma unroll
    for (int j = 0; j < 3; j++) { acc0[j] = 0ull; acc1[j] = 0ull; uacc[j] = 0ull; }
    const ull msk = 0x7FFFFFFF7FFFFFFFULL;

    // ---------------- Phase A: pipelined over 8 ck-chunks ----------------
#pragma unroll 1
    for (int ch = 0; ch < 8; ch++) {
        cp_wait0();
        __syncthreads();
        if (ch + 1 < 8) {
            int nb = (ch + 1) & 1;
            int ckn = (ch + 1) * 32;
#pragma unroll
            for (int i = 0; i < 12; i++) {
                int f = tid + 128 * i;
                int st = f >> 8;
                int rem = f & 255;
                int row = rem >> 3;
                int c4 = rem & 7;
                int s = st * 32 + row;
                bool ok = s < N_;
                cp16(s2u(&sm->u.pa.XLs[nb][st][row][c4 * 4]),
                     &xlh[(size_t)(ok ? s : 0) * HC_ + ckn + c4 * 4], ok);
            }
            cp_commit();
        }
        int bf = ch & 1;
        int ck = ch * 32;
#pragma unroll
        for (int c4 = 0; c4 < 8; c4++) {
            ulonglong2 r0 = *(const ulonglong2*)&sm->u.pa.XR[ty * 2][ck + c4 * 4];
            ulonglong2 r1 = *(const ulonglong2*)&sm->u.pa.XR[ty * 2 + 1][ck + c4 * 4];
            ulonglong2 a4 = *(const ulonglong2*)&sm->u.pa.A4[ck + c4 * 4];
            // w accumulators (uniform across lanes; 4 packed fmas per c4)
            asm("fma.rn.f32x2 %0, %1, %2, %0;" : "+l"(wacc0) : "l"(a4.x), "l"(r0.x));
            asm("fma.rn.f32x2 %0, %1, %2, %0;" : "+l"(wacc0) : "l"(a4.y), "l"(r0.y));
            asm("fma.rn.f32x2 %0, %1, %2, %0;" : "+l"(wacc1) : "l"(a4.x), "l"(r1.x));
            asm("fma.rn.f32x2 %0, %1, %2, %0;" : "+l"(wacc1) : "l"(a4.y), "l"(r1.y));
#pragma unroll
            for (int j = 0; j < 3; j++) {
                ulonglong2 l = *(const ulonglong2*)&sm->u.pa.XLs[bf][hf * 3 + j][lane][c4 * 4];
                ull s, m;
                // u accumulator for this band's s-value
                asm("fma.rn.f32x2 %0, %1, %2, %0;" : "+l"(uacc[j]) : "l"(a4.x), "l"(l.x));
                asm("fma.rn.f32x2 %0, %1, %2, %0;" : "+l"(uacc[j]) : "l"(a4.y), "l"(l.y));
                asm("add.rn.f32x2 %0, %1, %2;" : "=l"(s) : "l"(l.x), "l"(r0.x));
                asm("and.b64 %0, %1, %2;"      : "=l"(m) : "l"(s), "l"(msk));
                asm("fma.rn.f32x2 %0, %1, %2, %0;" : "+l"(acc0[j]) : "l"(m), "l"(a4.x));
                asm("add.rn.f32x2 %0, %1, %2;" : "=l"(s) : "l"(l.y), "l"(r0.y));
                asm("and.b64 %0, %1, %2;"      : "=l"(m) : "l"(s), "l"(msk));
                asm("fma.rn.f32x2 %0, %1, %2, %0;" : "+l"(acc0[j]) : "l"(m), "l"(a4.y));
                asm("add.rn.f32x2 %0, %1, %2;" : "=l"(s) : "l"(l.x), "l"(r1.x));
                asm("and.b64 %0, %1, %2;"      : "=l"(m) : "l"(s), "l"(msk));
                asm("fma.rn.f32x2 %0, %1, %2, %0;" : "+l"(acc1[j]) : "l"(m), "l"(a4.x));
                asm("add.rn.f32x2 %0, %1, %2;" : "=l"(s) : "l"(l.y), "l"(r1.y));
                asm("and.b64 %0, %1, %2;"      : "=l"(m) : "l"(s), "l"(msk));
                asm("fma.rn.f32x2 %0, %1, %2, %0;" : "+l"(acc1[j]) : "l"(m), "l"(a4.y));
            }
        }
        __syncthreads();
    }

    // ---- prefetch phase-B chunk 0 now; softmax hides its latency ----
#pragma unroll
    for (int i = 0; i < 16; i++) {
        int f = tid + 128 * i;          // 2048 float4
        int row = f >> 6, col4 = f & 63;
        int s = row;
        bool ok = s < N_;
        cp16(s2u(&sm->u.pb.Xs[0][row][col4 * 4]),
             &xlh[(size_t)(ok ? s : 0) * HC_ + col4 * 4], ok);
    }
    cp_commit();

    // ---------------- softmax (u/w folded from packed accumulators) ------
    float w_d0, w_d1;
    {
        float lo = __uint_as_float((unsigned)(wacc0 & 0xffffffffu));
        float hi = __uint_as_float((unsigned)(wacc0 >> 32));
        w_d0 = 2.5f * (lo + hi);
        lo = __uint_as_float((unsigned)(wacc1 & 0xffffffffu));
        hi = __uint_as_float((unsigned)(wacc1 >> 32));
        w_d1 = 2.5f * (lo + hi);
    }
    float lg0[3], lg1[3];
    float mx0 = -1e30f, mx1 = -1e30f;
#pragma unroll
    for (int j = 0; j < 3; j++) {
        int s = (hf * 3 + j) * 32 + lane;
        float ulo = __uint_as_float((unsigned)(uacc[j] & 0xffffffffu));
        float uhi = __uint_as_float((unsigned)(uacc[j] >> 32));
        float uv = 2.5f * (ulo + uhi);
        {
            ull a = acc0[j];
            float lo = __uint_as_float((unsigned)(a & 0xffffffffu));
            float hi = __uint_as_float((unsigned)(a >> 32));
            float v = 0.6f * (uv + w_d0) + lo + hi;
            if (s >= N_ || s == d0) v = -1e30f;
            lg0[j] = v;
            mx0 = fmaxf(mx0, v);
        }
        {
            ull a = acc1[j];
            float lo = __uint_as_float((unsigned)(a & 0xffffffffu));
            float hi = __uint_as_float((unsigned)(a >> 32));
            float v = 0.6f * (uv + w_d1) + lo + hi;
            if (s >= N_ || s == d1) v = -1e30f;
            lg1[j] = v;
            mx1 = fmaxf(mx1, v);
        }
    }
#pragma unroll
    for (int o = 16; o; o >>= 1) {
        mx0 = fmaxf(mx0, __shfl_xor_sync(0xffffffffu, mx0, o));
        mx1 = fmaxf(mx1, __shfl_xor_sync(0xffffffffu, mx1, o));
    }
    if (lane == 0) {
        sm->MX[ty * 2][hf]     = mx0;
        sm->MX[ty * 2 + 1][hf] = mx1;
    }
    __syncthreads();
    float gmx0 = fmaxf(sm->MX[ty * 2][0],     sm->MX[ty * 2][1]);
    float gmx1 = fmaxf(sm->MX[ty * 2 + 1][0], sm->MX[ty * 2 + 1][1]);
    float sum0 = 0.f, sum1 = 0.f;
#pragma unroll
    for (int j = 0; j < 3; j++) {
        float e0 = __expf(lg0[j] - gmx0);
        float e1 = __expf(lg1[j] - gmx1);
        lg0[j] = e0; lg1[j] = e1;
        sum0 += e0; sum1 += e1;
    }
#pragma unroll
    for (int o = 16; o; o >>= 1) {
        sum0 += __shfl_xor_sync(0xffffffffu, sum0, o);
        sum1 += __shfl_xor_sync(0xffffffffu, sum1, o);
    }
    if (lane == 0) {
        sm->SS[ty * 2][hf]     = sum0;
        sm->SS[ty * 2 + 1][hf] = sum1;
    }
    __syncthreads();
    float inv0 = 1.f / (sm->SS[ty * 2][0]     + sm->SS[ty * 2][1]     + 1e-16f);
    float inv1 = 1.f / (sm->SS[ty * 2 + 1][0] + sm->SS[ty * 2 + 1][1] + 1e-16f);
#pragma unroll
    for (int j = 0; j < 3; j++) {
        sm->AL[ty * 2][(hf * 3 + j) * 32 + lane]     = lg0[j] * inv0;
        sm->AL[ty * 2 + 1][(hf * 3 + j) * 32 + lane] = lg1[j] * inv1;
    }
    // AL write -> read ordering provided by the __syncthreads at phase-B loop head

    // ---------------- Phase B: warp = (d-pair, c-half) -------------------
    float4 accA = make_float4(0.f, 0.f, 0.f, 0.f);   // d0
    float4 accB = make_float4(0.f, 0.f, 0.f, 0.f);   // d1
    int cb = hf * 128 + lane * 4;
#pragma unroll 1
    for (int ch = 0; ch < 6; ch++) {
        cp_wait0();
        __syncthreads();
        if (ch + 1 < 6) {
            int nb = (ch + 1) & 1;
            int skn = (ch + 1) * 32;
#pragma unroll
            for (int i = 0; i < 16; i++) {
                int f = tid + 128 * i;
                int row = f >> 6, col4 = f & 63;
                int s = skn + row;
                bool ok = s < N_;
                cp16(s2u(&sm->u.pb.Xs[nb][row][col4 * 4]),
                     &xlh[(size_t)(ok ? s : 0) * HC_ + col4 * 4], ok);
            }
            cp_commit();
        }
        int bf = ch & 1;
        int sk = ch * 32;
#pragma unroll
        for (int k = 0; k < 32; k++) {
            float av0 = sm->AL[ty * 2][sk + k];
            float av1 = sm->AL[ty * 2 + 1][sk + k];
            float4 x = *(const float4*)&sm->u.pb.Xs[bf][k][cb];
            accA.x = fmaf(av0, x.x, accA.x); accA.y = fmaf(av0, x.y, accA.y);
            accA.z = fmaf(av0, x.z, accA.z); accA.w = fmaf(av0, x.w, accA.w);
            accB.x = fmaf(av1, x.x, accB.x); accB.y = fmaf(av1, x.y, accB.y);
            accB.z = fmaf(av1, x.z, accB.z); accB.w = fmaf(av1, x.w, accB.w);
        }
        __syncthreads();
    }

    if (dok0)
        *(float4*)&agg[((size_t)bh * N_ + d0) * C_ + cb] = accA;
    if (dok1)
        *(float4*)&agg[((size_t)bh * N_ + d1) * C_ + cb] = accB;
}

// ---------------- fused xl/xr GEMM: 64x64 tile, 4x4/thread, cp.async --------
__global__ __launch_bounds__(256) void gemm_dual(const float* __restrict__ A,
                                                 const float* __restrict__ B1,
                                                 const float* __restrict__ c1,
                                                 float* __restrict__ o1,
                                                 const float* __restrict__ B2,
                                                 const float* __restrict__ c2p,
                                                 float* __restrict__ o2,
                                                 int M, int K)
{
    __shared__ __align__(16) float As[2][64][36];
    __shared__ __align__(16) float Bs[2][32][68];

    const float* Bm;
    const float* bias;
    float* out;
    int n0;
    if (blockIdx.x < 16) { Bm = B1; bias = c1;  out = o1; n0 = blockIdx.x * 64; }
    else                 { Bm = B2; bias = c2p; out = o2; n0 = (blockIdx.x - 16) * 64; }

    int tid = threadIdx.x;
    int tx = tid & 15, ty = tid >> 4;
    int m0 = blockIdx.y * 64;

    int a_row = tid >> 2, a_c4a = (tid & 3) * 2;
    int b_row0 = tid >> 4, b_c4 = tid & 15;

    {
        bool okA = (m0 + a_row) < M;
        const float* srcA = &A[(size_t)(m0 + (okA ? a_row : 0)) * K + a_c4a * 4];
        cp16(s2u(&As[0][a_row][a_c4a * 4]), srcA, okA);
        cp16(s2u(&As[0][a_row][(a_c4a + 1) * 4]), srcA + 4, okA);
        cp16(s2u(&Bs[0][b_row0][b_c4 * 4]),
             &Bm[(size_t)b_row0 * HC_ + n0 + b_c4 * 4], true);
        cp16(s2u(&Bs[0][b_row0 + 16][b_c4 * 4]),
             &Bm[(size_t)(b_row0 + 16) * HC_ + n0 + b_c4 * 4], true);
    }
    cp_commit();

    float acc[4][4];
#pragma unroll
    for (int i = 0; i < 4; i++)
#pragma unroll
        for (int j = 0; j < 4; j++) acc[i][j] = 0.f;

    int nch = K / 32;
#pragma unroll 1
    for (int ch = 0; ch < nch; ch++) {
        cp_wait0();
        __syncthreads();
        if (ch + 1 < nch) {
            int nb = (ch + 1) & 1;
            int kkn = (ch + 1) * 32;
            bool okA = (m0 + a_row) < M;
            const float* srcA = &A[(size_t)(m0 + (okA ? a_row : 0)) * K + kkn + a_c4a * 4];
            cp16(s2u(&As[nb][a_row][a_c4a * 4]), srcA, okA);
            cp16(s2u(&As[nb][a_row][(a_c4a + 1) * 4]), srcA + 4, okA);
            cp16(s2u(&Bs[nb][b_row0][b_c4 * 4]),
                 &Bm[(size_t)(kkn + b_row0) * HC_ + n0 + b_c4 * 4], true);
            cp16(s2u(&Bs[nb][b_row0 + 16][b_c4 * 4]),
                 &Bm[(size_t)(kkn + b_row0 + 16) * HC_ + n0 + b_c4 * 4], true);
            cp_commit();
        }
        int bf = ch & 1;
#pragma unroll
        for (int k = 0; k < 32; k++) {
            float a0 = As[bf][ty * 4 + 0][k];
            float a1 = As[bf][ty * 4 + 1][k];
            float a2 = As[bf][ty * 4 + 2][k];
            float a3 = As[bf][ty * 4 + 3][k];
            float4 bv = *(const float4*)&Bs[bf][k][tx * 4];
            acc[0][0] = fmaf(a0, bv.x, acc[0][0]); acc[0][1] = fmaf(a0, bv.y, acc[0][1]);
            acc[0][2] = fmaf(a0, bv.z, acc[0][2]); acc[0][3] = fmaf(a0, bv.w, acc[0][3]);
            acc[1][0] = fmaf(a1, bv.x, acc[1][0]); acc[1][1] = fmaf(a1, bv.y, acc[1][1]);
            acc[1][2] = fmaf(a1, bv.z, acc[1][2]); acc[1][3] = fmaf(a1, bv.w, acc[1][3]);
            acc[2][0] = fmaf(a2, bv.x, acc[2][0]); acc[2][1] = fmaf(a2, bv.y, acc[2][1]);
            acc[2][2] = fmaf(a2, bv.z, acc[2][2]); acc[2][3] = fmaf(a2, bv.w, acc[2][3]);
            acc[3][0] = fmaf(a3, bv.x, acc[3][0]); acc[3][1] = fmaf(a3, bv.y, acc[3][1]);
            acc[3][2] = fmaf(a3, bv.z, acc[3][2]); acc[3][3] = fmaf(a3, bv.w, acc[3][3]);
        }
        __syncthreads();
    }

    float4 bb = *(const float4*)&bias[n0 + tx * 4];
#pragma unroll
    for (int i = 0; i < 4; i++) {
        int r = m0 + ty * 4 + i;
        if (r < M) {
            float4 o4;
            o4.x = acc[i][0] + bb.x;
            o4.y = acc[i][1] + bb.y;
            o4.z = acc[i][2] + bb.z;
            o4.w = acc[i][3] + bb.w;
            *(float4*)&out[(size_t)r * HC_ + n0 + tx * 4] = o4;
        }
    }
}

// ---------------- generic 32x32 GEMM, cp.async double-buffered --------------
// mode: 1 relu, 2 residual: out = resid + acc + bias
__global__ void gemm_kernel(const float* __restrict__ A,
                            const float* __restrict__ Bm,
                            const float* __restrict__ bias,
                            const float* __restrict__ resid,
                            float* __restrict__ out,
                            int M, int N, int K, int mode)
{
    __shared__ __align__(16) float As[2][32][36];
    __shared__ __align__(16) float Bs[2][32][36];
    int tid = threadIdx.x;
    int tx = tid & 15, ty = tid >> 4;
    int m0 = blockIdx.y * 32;
    int n0 = blockIdx.x * 32;
    int lr = tid >> 3, lc4 = tid & 7;
    float a00 = 0.f, a01 = 0.f, a10 = 0.f, a11 = 0.f;

    {
        bool okA = (m0 + lr) < M;
        cp16(s2u(&As[0][lr][lc4 * 4]),
             &A[(size_t)(m0 + (okA ? lr : 0)) * K + lc4 * 4], okA);
        cp16(s2u(&Bs[0][lr][lc4 * 4]),
             &Bm[(size_t)lr * N + n0 + lc4 * 4], true);
    }
    cp_commit();

    int nch = K / 32;
#pragma unroll 1
    for (int ch = 0; ch < nch; ch++) {
        cp_wait0();
        __syncthreads();
        if (ch + 1 < nch) {
            int nb = (ch + 1) & 1;
            int kkn = (ch + 1) * 32;
            bool okA = (m0 + lr) < M;
            cp16(s2u(&As[nb][lr][lc4 * 4]),
                 &A[(size_t)(m0 + (okA ? lr : 0)) * K + kkn + lc4 * 4], okA);
            cp16(s2u(&Bs[nb][lr][lc4 * 4]),
                 &Bm[(size_t)(kkn + lr) * N + n0 + lc4 * 4], true);
            cp_commit();
        }
        int bf = ch & 1;
#pragma unroll
        for (int k = 0; k < 32; k++) {
            float av0 = As[bf][ty][k],      av1 = As[bf][ty + 16][k];
            float bv0 = Bs[bf][k][tx],      bv1 = Bs[bf][k][tx + 16];
            a00 = fmaf(av0, bv0, a00);  a01 = fmaf(av0, bv1, a01);
            a10 = fmaf(av1, bv0, a10);  a11 = fmaf(av1, bv1, a11);
        }
        __syncthreads();
    }

    int r0 = m0 + ty, r1 = m0 + ty + 16;
    int c0 = n0 + tx, c1 = n0 + tx + 16;
    float b0 = bias[c0], b1 = bias[c1];
    if (mode == 1) {
        if (r0 < M) { out[r0 * N + c0] = fmaxf(a00 + b0, 0.f); out[r0 * N + c1] = fmaxf(a01 + b1, 0.f); }
        if (r1 < M) { out[r1 * N + c0] = fmaxf(a10 + b0, 0.f); out[r1 * N + c1] = fmaxf(a11 + b1, 0.f); }
    } else {
        if (r0 < M) {
            out[r0 * N + c0] = resid[r0 * N + c0] + a00 + b0;
            out[r0 * N + c1] = resid[r0 * N + c1] + a01 + b1;
        }
        if (r1 < M) {
            out[r1 * N + c0] = resid[r1 * N + c0] + a10 + b0;
            out[r1 * N + c1] = resid[r1 * N + c1] + a11 + b1;
        }
    }
}

// ---------------- head-mean + bias + layernorm: 2 warps/row, 338 blocks -----
__global__ __launch_bounds__(64) void ln_kernel(const float* __restrict__ agg,
                                                const float* __restrict__ bias_l,
                                                const float* __restrict__ g,
                                                const float* __restrict__ bt,
                                                float* __restrict__ out)
{
    int lane = threadIdx.x & 31;
    int wrp = threadIdx.x >> 5;
    int n = blockIdx.x;
    int b = (n >= N_) ? 1 : 0;
    int d = n - b * N_;
    int c = wrp * 128 + lane * 4;

    float4 v = make_float4(0.f, 0.f, 0.f, 0.f);
#pragma unroll
    for (int h = 0; h < H_; h++) {
        float4 t = *(const float4*)&agg[((size_t)(b * H_ + h) * N_ + d) * C_ + c];
        v.x += t.x; v.y += t.y; v.z += t.z; v.w += t.w;
    }
    float4 bb = *(const float4*)&bias_l[c];
    v.x = 0.25f * v.x + bb.x; v.y = 0.25f * v.y + bb.y;
    v.z = 0.25f * v.z + bb.z; v.w = 0.25f * v.w + bb.w;

    __shared__ float red[2][2];
    float s = v.x + v.y + v.z + v.w;
#pragma unroll
    for (int o = 16; o; o >>= 1) s += __shfl_xor_sync(0xffffffffu, s, o);
    if (lane == 0) red[0][wrp] = s;
    __syncthreads();
    float mu = (red[0][0] + red[0][1]) * (1.f / C_);

    float4 e = make_float4(v.x - mu, v.y - mu, v.z - mu, v.w - mu);
    float s2 = e.x * e.x + e.y * e.y + e.z * e.z + e.w * e.w;
#pragma unroll
    for (int o = 16; o; o >>= 1) s2 += __shfl_xor_sync(0xffffffffu, s2, o);
    if (lane == 0) red[1][wrp] = s2;
    __syncthreads();
    float rstd = rsqrtf((red[1][0] + red[1][1]) * (1.f / C_) + 1e-5f);

    float4 gg = *(const float4*)&g[c];
    float4 tb = *(const float4*)&bt[c];
    float4 o4;
    o4.x = e.x * rstd * gg.x + tb.x;
    o4.y = e.y * rstd * gg.y + tb.y;
    o4.z = e.z * rstd * gg.z + tb.z;
    o4.w = e.w * rstd * gg.w + tb.w;
    *(float4*)&out[(size_t)n * C_ + c] = o4;
}

// ---------------- final mean pool per graph ----------------------------------
__global__ void pool_kernel(const float* __restrict__ x, float* __restrict__ out)
{
    int b = blockIdx.x, t = threadIdx.x;
    float s = 0.f;
#pragma unroll 13
    for (int d = 0; d < N_; d++) s += x[(b * N_ + d) * C_ + t];
    out[b * C_ + t] = s * (1.f / N_);
}

// ---------------- host launcher -----------------------------------------------
extern "C" void kernel_launch(void* const* d_in, const int* in_sizes, int n_in,
                              void* d_out, int out_size)
{
    const float* x    = (const float*)d_in[0];
    const float* Wl   = (const float*)d_in[1];
    const float* bl   = (const float*)d_in[2];
    const float* Wr   = (const float*)d_in[3];
    const float* br   = (const float*)d_in[4];
    const float* att  = (const float*)d_in[5];
    const float* bias = (const float*)d_in[6];
    const float* lng  = (const float*)d_in[7];
    const float* lnb  = (const float*)d_in[8];
    const float* W1   = (const float*)d_in[9];
    const float* b1   = (const float*)d_in[10];
    const float* W2   = (const float*)d_in[11];
    const float* b2   = (const float*)d_in[12];

    float *bx, *bxl, *bxr, *bag, *bh, *bm;
    cudaGetSymbolAddress((void**)&bx,  g_x);
    cudaGetSymbolAddress((void**)&bxl, g_xl);
    cudaGetSymbolAddress((void**)&bxr, g_xr);
    cudaGetSymbolAddress((void**)&bag, g_agg);
    cudaGetSymbolAddress((void**)&bh,  g_h);
    cudaGetSymbolAddress((void**)&bm,  g_m);

    static int attr_done = 0;
    if (!attr_done) {
        cudaFuncSetAttribute(attn_agg_kernel,
                             cudaFuncAttributeMaxDynamicSharedMemorySize,
                             (int)ATTN_SMEM_BYTES);
        attr_done = 1;
    }

    for (int l = 0; l < L_; l++) {
        const float* xin = (l == 0) ? x : bx;
        gemm_dual<<<dim3(32, 6), 256>>>(xin,
                                        Wl + l * C_ * HC_, bl + l * HC_, bxl,
                                        Wr + l * C_ * HC_, br + l * HC_, bxr,
                                        NN_, C_);
        attn_agg_kernel<<<dim3(43, 8), 128, ATTN_SMEM_BYTES>>>(
            bxl, bxr, att + l * H_ * C_, bag);
        ln_kernel<<<NN_, 64>>>(bag, bias + l * C_, lng + l * C_, lnb + l * C_, bh);
        gemm_kernel<<<dim3(16, 11), 256>>>(bh, W1 + l * C_ * 2 * C_, b1 + l * 2 * C_,
                                           nullptr, bm, NN_, 2 * C_, C_, 1);
        gemm_kernel<<<dim3(8, 11), 256>>>(bm, W2 + l * 2 * C_ * C_, b2 + l * C_,
                                          xin, bx, NN_, C_, 2 * C_, 2);
    }

    pool_kernel<<<B_, 256>>>(bx, (float*)d_out);
}

// round 16
// speedup vs baseline: 1.0170x; 1.0170x over previous
#include <cuda_runtime.h>

#define B_   2
#define N_   169
#define NN_  338
#define C_   256
#define H_   4
#define HC_  1024
#define L_   3

typedef unsigned long long ull;

// ---------------- scratch (device globals) ---------------------------------
__device__ float g_x[NN_ * C_];               // running node features
__device__ float g_xl[NN_ * HC_];             // x @ Wl + bl
__device__ float g_xr[NN_ * HC_];             // x @ Wr + br
__device__ float g_agg[B_ * H_ * N_ * C_];    // per-head aggregation partials
__device__ float g_h[NN_ * C_];               // post layernorm
__device__ float g_m[NN_ * 2 * C_];           // mlp hidden
__device__ float g_u[H_ * NN_];               // <att, xl_n> per head
__device__ float g_w[H_ * NN_];               // <att, xr_n> per head

// ---------------- cp.async helpers ------------------------------------------
__device__ __forceinline__ unsigned s2u(const void* p)
{
    return (unsigned)__cvta_generic_to_shared(p);
}
__device__ __forceinline__ void cp16(unsigned dst, const void* src, bool ok)
{
    int sz = ok ? 16 : 0;
    asm volatile("cp.async.cg.shared.global [%0], [%1], 16, %2;"
                 :: "r"(dst), "l"(src), "r"(sz));
}
__device__ __forceinline__ void cp_commit()
{
    asm volatile("cp.async.commit_group;");
}
__device__ __forceinline__ void cp_wait0()
{
    asm volatile("cp.async.wait_group 0;" ::: "memory");
}

// ---------------- u/w rank-1 terms: u[h,n]=<att_h, xl[n,h,:]>, w likewise ---
__global__ __launch_bounds__(128) void uw_kernel(const float* __restrict__ xl,
                                                 const float* __restrict__ xr,
                                                 const float* __restrict__ att_l,
                                                 float* __restrict__ u,
                                                 float* __restrict__ w)
{
    int n = blockIdx.x;
    int h = threadIdx.x >> 5, lane = threadIdx.x & 31;
    const float4* xlp = (const float4*)&xl[(size_t)n * HC_ + h * C_];
    const float4* xrp = (const float4*)&xr[(size_t)n * HC_ + h * C_];
    const float4* ap  = (const float4*)&att_l[h * C_];
    float su = 0.f, sw = 0.f;
#pragma unroll
    for (int i = 0; i < 2; i++) {
        float4 a = ap[lane + 32 * i];
        float4 vl = xlp[lane + 32 * i];
        float4 vr = xrp[lane + 32 * i];
        su += a.x * vl.x + a.y * vl.y + a.z * vl.z + a.w * vl.w;
        sw += a.x * vr.x + a.y * vr.y + a.z * vr.z + a.w * vr.w;
    }
#pragma unroll
    for (int o = 16; o; o >>= 1) {
        su += __shfl_xor_sync(0xffffffffu, su, o);
        sw += __shfl_xor_sync(0xffffffffu, sw, o);
    }
    if (lane == 0) {
        u[h * NN_ + n] = su;
        w[h * NN_ + n] = sw;
    }
}

// ---------------- fused logits + softmax + aggregation ----------------------
// grid (43 d-tiles, 8 bh), block 128 = 4 warps. (R14 proven config)
struct AttnSmem {
    union {
        struct {
            float XLs[2][6][32][36];
            float XR[4][256];
            float A4[256];
        } pa;
        struct {
            float Xs[2][32][260];
        } pb;
    } u;
    float AL[4][193];
    float MX[4][2];
    float SS[4][2];
};
#define ATTN_SMEM_BYTES sizeof(AttnSmem)

__global__ __launch_bounds__(128) void attn_agg_kernel(const float* __restrict__ xl,
                                                       const float* __restrict__ xr,
                                                       const float* __restrict__ att_l,
                                                       const float* __restrict__ u,
                                                       const float* __restrict__ w,
                                                       float* __restrict__ agg)
{
    extern __shared__ __align__(16) char smem_raw[];
    AttnSmem* sm = (AttnSmem*)smem_raw;

    int tid = threadIdx.x;
    int lane = tid & 31;
    int wid = tid >> 5;
    int ty = wid >> 1;            // d-pair 0..1
    int hf = wid & 1;             // s-half: bands {0,1,2} or {3,4,5}
    int dt = blockIdx.x, bh = blockIdx.y;
    int b = bh >> 2, h = bh & 3;
    int d0 = dt * 4 + ty * 2;
    int d1 = d0 + 1;
    bool dok0 = d0 < N_, dok1 = d1 < N_;

    const float* xlh = xl + (size_t)b * N_ * HC_ + h * C_;

    // ---- stage chunk 0 of XLs (cp16), then XR + A4 (sync LDG, once) ----
#pragma unroll
    for (int i = 0; i < 12; i++) {
        int f = tid + 128 * i;          // 1536 float4 total
        int st = f >> 8;
        int rem = f & 255;
        int row = rem >> 3;
        int c4 = rem & 7;
        int s = st * 32 + row;
        bool ok = s < N_;
        cp16(s2u(&sm->u.pa.XLs[0][st][row][c4 * 4]),
             &xlh[(size_t)(ok ? s : 0) * HC_ + c4 * 4], ok);
    }
    cp_commit();
#pragma unroll
    for (int i = 0; i < 4; i++) {
        int f = tid + 128 * i;          // 512 float2 for XR[4][256]
        int row = f >> 7;
        int cc = (f & 127) * 2;
        int dr = dt * 4 + row;
        float2 v = make_float2(0.f, 0.f);
        if (dr < N_) v = *(const float2*)&xr[(size_t)(b * N_ + dr) * HC_ + h * C_ + cc];
        *(float2*)&sm->u.pa.XR[row][cc] = v;
    }
    {
        float2 a = *(const float2*)&att_l[h * C_ + tid * 2];
        sm->u.pa.A4[tid * 2]     = 0.4f * a.x;
        sm->u.pa.A4[tid * 2 + 1] = 0.4f * a.y;
    }

    ull acc0[3], acc1[3];
#pragma unroll
    for (int j = 0; j < 3; j++) { acc0[j] = 0ull; acc1[j] = 0ull; }
    const ull msk = 0x7FFFFFFF7FFFFFFFULL;

    // ---------------- Phase A: pipelined over 8 ck-chunks ----------------
#pragma unroll 1
    for (int ch = 0; ch < 8; ch++) {
        cp_wait0();
        __syncthreads();
        if (ch + 1 < 8) {
            int nb = (ch + 1) & 1;
            int ckn = (ch + 1) * 32;
#pragma unroll
            for (int i = 0; i < 12; i++) {
                int f = tid + 128 * i;
                int st = f >> 8;
                int rem = f & 255;
                int row = rem >> 3;
                int c4 = rem & 7;
                int s = st * 32 + row;
                bool ok = s < N_;
                cp16(s2u(&sm->u.pa.XLs[nb][st][row][c4 * 4]),
                     &xlh[(size_t)(ok ? s : 0) * HC_ + ckn + c4 * 4], ok);
            }
            cp_commit();
        }
        int bf = ch & 1;
        int ck = ch * 32;
#pragma unroll
        for (int c4 = 0; c4 < 8; c4++) {
            ulonglong2 r0 = *(const ulonglong2*)&sm->u.pa.XR[ty * 2][ck + c4 * 4];
            ulonglong2 r1 = *(const ulonglong2*)&sm->u.pa.XR[ty * 2 + 1][ck + c4 * 4];
            ulonglong2 a4 = *(const ulonglong2*)&sm->u.pa.A4[ck + c4 * 4];
#pragma unroll
            for (int j = 0; j < 3; j++) {
                ulonglong2 l = *(const ulonglong2*)&sm->u.pa.XLs[bf][hf * 3 + j][lane][c4 * 4];
                ull s, m;
                asm("add.rn.f32x2 %0, %1, %2;" : "=l"(s) : "l"(l.x), "l"(r0.x));
                asm("and.b64 %0, %1, %2;"      : "=l"(m) : "l"(s), "l"(msk));
                asm("fma.rn.f32x2 %0, %1, %2, %0;" : "+l"(acc0[j]) : "l"(m), "l"(a4.x));
                asm("add.rn.f32x2 %0, %1, %2;" : "=l"(s) : "l"(l.y), "l"(r0.y));
                asm("and.b64 %0, %1, %2;"      : "=l"(m) : "l"(s), "l"(msk));
                asm("fma.rn.f32x2 %0, %1, %2, %0;" : "+l"(acc0[j]) : "l"(m), "l"(a4.y));
                asm("add.rn.f32x2 %0, %1, %2;" : "=l"(s) : "l"(l.x), "l"(r1.x));
                asm("and.b64 %0, %1, %2;"      : "=l"(m) : "l"(s), "l"(msk));
                asm("fma.rn.f32x2 %0, %1, %2, %0;" : "+l"(acc1[j]) : "l"(m), "l"(a4.x));
                asm("add.rn.f32x2 %0, %1, %2;" : "=l"(s) : "l"(l.y), "l"(r1.y));
                asm("and.b64 %0, %1, %2;"      : "=l"(m) : "l"(s), "l"(msk));
                asm("fma.rn.f32x2 %0, %1, %2, %0;" : "+l"(acc1[j]) : "l"(m), "l"(a4.y));
            }
        }
        __syncthreads();
    }

    // ---- prefetch phase-B chunk 0 now; softmax hides its latency ----
#pragma unroll
    for (int i = 0; i < 16; i++) {
        int f = tid + 128 * i;          // 2048 float4
        int row = f >> 6, col4 = f & 63;
        int s = row;
        bool ok = s < N_;
        cp16(s2u(&sm->u.pb.Xs[0][row][col4 * 4]),
             &xlh[(size_t)(ok ? s : 0) * HC_ + col4 * 4], ok);
    }
    cp_commit();

    // ---------------- softmax (2 d-rows per warp, 2-warp combine) --------
    float w_d0 = dok0 ? w[h * NN_ + b * N_ + d0] : 0.f;
    float w_d1 = dok1 ? w[h * NN_ + b * N_ + d1] : 0.f;
    float lg0[3], lg1[3];
    float mx0 = -1e30f, mx1 = -1e30f;
#pragma unroll
    for (int j = 0; j < 3; j++) {
        int s = (hf * 3 + j) * 32 + lane;
        float uv = (s < N_) ? u[h * NN_ + b * N_ + s] : 0.f;
        {
            ull a = acc0[j];
            float lo = __uint_as_float((unsigned)(a & 0xffffffffu));
            float hi = __uint_as_float((unsigned)(a >> 32));
            float v = 0.6f * (uv + w_d0) + lo + hi;
            if (s >= N_ || s == d0) v = -1e30f;
            lg0[j] = v;
            mx0 = fmaxf(mx0, v);
        }
        {
            ull a = acc1[j];
            float lo = __uint_as_float((unsigned)(a & 0xffffffffu));
            float hi = __uint_as_float((unsigned)(a >> 32));
            float v = 0.6f * (uv + w_d1) + lo + hi;
            if (s >= N_ || s == d1) v = -1e30f;
            lg1[j] = v;
            mx1 = fmaxf(mx1, v);
        }
    }
#pragma unroll
    for (int o = 16; o; o >>= 1) {
        mx0 = fmaxf(mx0, __shfl_xor_sync(0xffffffffu, mx0, o));
        mx1 = fmaxf(mx1, __shfl_xor_sync(0xffffffffu, mx1, o));
    }
    if (lane == 0) {
        sm->MX[ty * 2][hf]     = mx0;
        sm->MX[ty * 2 + 1][hf] = mx1;
    }
    __syncthreads();
    float gmx0 = fmaxf(sm->MX[ty * 2][0],     sm->MX[ty * 2][1]);
    float gmx1 = fmaxf(sm->MX[ty * 2 + 1][0], sm->MX[ty * 2 + 1][1]);
    float sum0 = 0.f, sum1 = 0.f;
#pragma unroll
    for (int j = 0; j < 3; j++) {
        float e0 = __expf(lg0[j] - gmx0);
        float e1 = __expf(lg1[j] - gmx1);
        lg0[j] = e0; lg1[j] = e1;
        sum0 += e0; sum1 += e1;
    }
#pragma unroll
    for (int o = 16; o; o >>= 1) {
        sum0 += __shfl_xor_sync(0xffffffffu, sum0, o);
        sum1 += __shfl_xor_sync(0xffffffffu, sum1, o);
    }
    if (lane == 0) {
        sm->SS[ty * 2][hf]     = sum0;
        sm->SS[ty * 2 + 1][hf] = sum1;
    }
    __syncthreads();
    float inv0 = 1.f / (sm->SS[ty * 2][0]     + sm->SS[ty * 2][1]     + 1e-16f);
    float inv1 = 1.f / (sm->SS[ty * 2 + 1][0] + sm->SS[ty * 2 + 1][1] + 1e-16f);
#pragma unroll
    for (int j = 0; j < 3; j++) {
        sm->AL[ty * 2][(hf * 3 + j) * 32 + lane]     = lg0[j] * inv0;
        sm->AL[ty * 2 + 1][(hf * 3 + j) * 32 + lane] = lg1[j] * inv1;
    }
    // AL write -> read ordering provided by the __syncthreads at phase-B loop head

    // ---------------- Phase B: warp = (d-pair, c-half) -------------------
    float4 accA = make_float4(0.f, 0.f, 0.f, 0.f);   // d0
    float4 accB = make_float4(0.f, 0.f, 0.f, 0.f);   // d1
    int cb = hf * 128 + lane * 4;
#pragma unroll 1
    for (int ch = 0; ch < 6; ch++) {
        cp_wait0();
        __syncthreads();
        if (ch + 1 < 6) {
            int nb = (ch + 1) & 1;
            int skn = (ch + 1) * 32;
#pragma unroll
            for (int i = 0; i < 16; i++) {
                int f = tid + 128 * i;
                int row = f >> 6, col4 = f & 63;
                int s = skn + row;
                bool ok = s < N_;
                cp16(s2u(&sm->u.pb.Xs[nb][row][col4 * 4]),
                     &xlh[(size_t)(ok ? s : 0) * HC_ + col4 * 4], ok);
            }
            cp_commit();
        }
        int bf = ch & 1;
        int sk = ch * 32;
#pragma unroll
        for (int k = 0; k < 32; k++) {
            float av0 = sm->AL[ty * 2][sk + k];
            float av1 = sm->AL[ty * 2 + 1][sk + k];
            float4 x = *(const float4*)&sm->u.pb.Xs[bf][k][cb];
            accA.x = fmaf(av0, x.x, accA.x); accA.y = fmaf(av0, x.y, accA.y);
            accA.z = fmaf(av0, x.z, accA.z); accA.w = fmaf(av0, x.w, accA.w);
            accB.x = fmaf(av1, x.x, accB.x); accB.y = fmaf(av1, x.y, accB.y);
            accB.z = fmaf(av1, x.z, accB.z); accB.w = fmaf(av1, x.w, accB.w);
        }
        __syncthreads();
    }

    if (dok0)
        *(float4*)&agg[((size_t)bh * N_ + d0) * C_ + cb] = accA;
    if (dok1)
        *(float4*)&agg[((size_t)bh * N_ + d1) * C_ + cb] = accB;
}

// ---------------- fused xl/xr GEMM: 64x64 tile, 4x4/thread, cp.async --------
__global__ __launch_bounds__(256) void gemm_dual(const float* __restrict__ A,
                                                 const float* __restrict__ B1,
                                                 const float* __restrict__ c1,
                                                 float* __restrict__ o1,
                                                 const float* __restrict__ B2,
                                                 const float* __restrict__ c2p,
                                                 float* __restrict__ o2,
                                                 int M, int K)
{
    __shared__ __align__(16) float As[2][64][36];
    __shared__ __align__(16) float Bs[2][32][68];

    const float* Bm;
    const float* bias;
    float* out;
    int n0;
    if (blockIdx.x < 16) { Bm = B1; bias = c1;  out = o1; n0 = blockIdx.x * 64; }
    else                 { Bm = B2; bias = c2p; out = o2; n0 = (blockIdx.x - 16) * 64; }

    int tid = threadIdx.x;
    int tx = tid & 15, ty = tid >> 4;
    int m0 = blockIdx.y * 64;

    int a_row = tid >> 2, a_c4a = (tid & 3) * 2;
    int b_row0 = tid >> 4, b_c4 = tid & 15;

    {
        bool okA = (m0 + a_row) < M;
        const float* srcA = &A[(size_t)(m0 + (okA ? a_row : 0)) * K + a_c4a * 4];
        cp16(s2u(&As[0][a_row][a_c4a * 4]), srcA, okA);
        cp16(s2u(&As[0][a_row][(a_c4a + 1) * 4]), srcA + 4, okA);
        cp16(s2u(&Bs[0][b_row0][b_c4 * 4]),
             &Bm[(size_t)b_row0 * HC_ + n0 + b_c4 * 4], true);
        cp16(s2u(&Bs[0][b_row0 + 16][b_c4 * 4]),
             &Bm[(size_t)(b_row0 + 16) * HC_ + n0 + b_c4 * 4], true);
    }
    cp_commit();

    float acc[4][4];
#pragma unroll
    for (int i = 0; i < 4; i++)
#pragma unroll
        for (int j = 0; j < 4; j++) acc[i][j] = 0.f;

    int nch = K / 32;
#pragma unroll 1
    for (int ch = 0; ch < nch; ch++) {
        cp_wait0();
        __syncthreads();
        if (ch + 1 < nch) {
            int nb = (ch + 1) & 1;
            int kkn = (ch + 1) * 32;
            bool okA = (m0 + a_row) < M;
            const float* srcA = &A[(size_t)(m0 + (okA ? a_row : 0)) * K + kkn + a_c4a * 4];
            cp16(s2u(&As[nb][a_row][a_c4a * 4]), srcA, okA);
            cp16(s2u(&As[nb][a_row][(a_c4a + 1) * 4]), srcA + 4, okA);
            cp16(s2u(&Bs[nb][b_row0][b_c4 * 4]),
                 &Bm[(size_t)(kkn + b_row0) * HC_ + n0 + b_c4 * 4], true);
            cp16(s2u(&Bs[nb][b_row0 + 16][b_c4 * 4]),
                 &Bm[(size_t)(kkn + b_row0 + 16) * HC_ + n0 + b_c4 * 4], true);
            cp_commit();
        }
        int bf = ch & 1;
#pragma unroll
        for (int k = 0; k < 32; k++) {
            float a0 = As[bf][ty * 4 + 0][k];
            float a1 = As[bf][ty * 4 + 1][k];
            float a2 = As[bf][ty * 4 + 2][k];
            float a3 = As[bf][ty * 4 + 3][k];
            float4 bv = *(const float4*)&Bs[bf][k][tx * 4];
            acc[0][0] = fmaf(a0, bv.x, acc[0][0]); acc[0][1] = fmaf(a0, bv.y, acc[0][1]);
            acc[0][2] = fmaf(a0, bv.z, acc[0][2]); acc[0][3] = fmaf(a0, bv.w, acc[0][3]);
            acc[1][0] = fmaf(a1, bv.x, acc[1][0]); acc[1][1] = fmaf(a1, bv.y, acc[1][1]);
            acc[1][2] = fmaf(a1, bv.z, acc[1][2]); acc[1][3] = fmaf(a1, bv.w, acc[1][3]);
            acc[2][0] = fmaf(a2, bv.x, acc[2][0]); acc[2][1] = fmaf(a2, bv.y, acc[2][1]);
            acc[2][2] = fmaf(a2, bv.z, acc[2][2]); acc[2][3] = fmaf(a2, bv.w, acc[2][3]);
            acc[3][0] = fmaf(a3, bv.x, acc[3][0]); acc[3][1] = fmaf(a3, bv.y, acc[3][1]);
            acc[3][2] = fmaf(a3, bv.z, acc[3][2]); acc[3][3] = fmaf(a3, bv.w, acc[3][3]);
        }
        __syncthreads();
    }

    float4 bb = *(const float4*)&bias[n0 + tx * 4];
#pragma unroll
    for (int i = 0; i < 4; i++) {
        int r = m0 + ty * 4 + i;
        if (r < M) {
            float4 o4;
            o4.x = acc[i][0] + bb.x;
            o4.y = acc[i][1] + bb.y;
            o4.z = acc[i][2] + bb.z;
            o4.w = acc[i][3] + bb.w;
            *(float4*)&out[(size_t)r * HC_ + n0 + tx * 4] = o4;
        }
    }
}

// ---------------- generic 32x32 GEMM, cp.async (MLP1: relu) -----------------
__global__ void gemm_kernel(const float* __restrict__ A,
                            const float* __restrict__ Bm,
                            const float* __restrict__ bias,
                            float* __restrict__ out,
                            int M, int N, int K)
{
    __shared__ __align__(16) float As[2][32][36];
    __shared__ __align__(16) float Bs[2][32][36];
    int tid = threadIdx.x;
    int tx = tid & 15, ty = tid >> 4;
    int m0 = blockIdx.y * 32;
    int n0 = blockIdx.x * 32;
    int lr = tid >> 3, lc4 = tid & 7;
    float a00 = 0.f, a01 = 0.f, a10 = 0.f, a11 = 0.f;

    {
        bool okA = (m0 + lr) < M;
        cp16(s2u(&As[0][lr][lc4 * 4]),
             &A[(size_t)(m0 + (okA ? lr : 0)) * K + lc4 * 4], okA);
        cp16(s2u(&Bs[0][lr][lc4 * 4]),
             &Bm[(size_t)lr * N + n0 + lc4 * 4], true);
    }
    cp_commit();

    int nch = K / 32;
#pragma unroll 1
    for (int ch = 0; ch < nch; ch++) {
        cp_wait0();
        __syncthreads();
        if (ch + 1 < nch) {
            int nb = (ch + 1) & 1;
            int kkn = (ch + 1) * 32;
            bool okA = (m0 + lr) < M;
            cp16(s2u(&As[nb][lr][lc4 * 4]),
                 &A[(size_t)(m0 + (okA ? lr : 0)) * K + kkn + lc4 * 4], okA);
            cp16(s2u(&Bs[nb][lr][lc4 * 4]),
                 &Bm[(size_t)(kkn + lr) * N + n0 + lc4 * 4], true);
            cp_commit();
        }
        int bf = ch & 1;
#pragma unroll
        for (int k = 0; k < 32; k++) {
            float av0 = As[bf][ty][k],      av1 = As[bf][ty + 16][k];
            float bv0 = Bs[bf][k][tx],      bv1 = Bs[bf][k][tx + 16];
            a00 = fmaf(av0, bv0, a00);  a01 = fmaf(av0, bv1, a01);
            a10 = fmaf(av1, bv0, a10);  a11 = fmaf(av1, bv1, a11);
        }
        __syncthreads();
    }

    int r0 = m0 + ty, r1 = m0 + ty + 16;
    int c0 = n0 + tx, c1 = n0 + tx + 16;
    float b0 = bias[c0], b1 = bias[c1];
    if (r0 < M) { out[r0 * N + c0] = fmaxf(a00 + b0, 0.f); out[r0 * N + c1] = fmaxf(a01 + b1, 0.f); }
    if (r1 < M) { out[r1 * N + c0] = fmaxf(a10 + b0, 0.f); out[r1 * N + c1] = fmaxf(a11 + b1, 0.f); }
}

// ---------------- 16x32-tile GEMM, 128 threads (MLP2: residual) -------------
// grid (N/32, ceil(M/16)) -> 176 blocks for M=338,N=256: full-chip spread.
__global__ __launch_bounds__(128) void gemm16_kernel(const float* __restrict__ A,
                                                     const float* __restrict__ Bm,
                                                     const float* __restrict__ bias,
                                                     const float* __restrict__ resid,
                                                     float* __restrict__ out,
                                                     int M, int N, int K)
{
    __shared__ __align__(16) float As[2][16][36];
    __shared__ __align__(16) float Bs[2][32][36];
    int tid = threadIdx.x;
    int tx = tid & 15, ty = tid >> 4;        // ty 0..7
    int m0 = blockIdx.y * 16;
    int n0 = blockIdx.x * 32;
    int a_row = tid >> 3, a_c4 = tid & 7;    // 16 rows x 8 c4 = 128
    float a00 = 0.f, a01 = 0.f, a10 = 0.f, a11 = 0.f;

    {
        bool okA = (m0 + a_row) < M;
        cp16(s2u(&As[0][a_row][a_c4 * 4]),
             &A[(size_t)(m0 + (okA ? a_row : 0)) * K + a_c4 * 4], okA);
        cp16(s2u(&Bs[0][a_row][a_c4 * 4]),
             &Bm[(size_t)a_row * N + n0 + a_c4 * 4], true);
        cp16(s2u(&Bs[0][a_row + 16][a_c4 * 4]),
             &Bm[(size_t)(a_row + 16) * N + n0 + a_c4 * 4], true);
    }
    cp_commit();

    int nch = K / 32;
#pragma unroll 1
    for (int ch = 0; ch < nch; ch++) {
        cp_wait0();
        __syncthreads();
        if (ch + 1 < nch) {
            int nb = (ch + 1) & 1;
            int kkn = (ch + 1) * 32;
            bool okA = (m0 + a_row) < M;
            cp16(s2u(&As[nb][a_row][a_c4 * 4]),
                 &A[(size_t)(m0 + (okA ? a_row : 0)) * K + kkn + a_c4 * 4], okA);
            cp16(s2u(&Bs[nb][a_row][a_c4 * 4]),
                 &Bm[(size_t)(kkn + a_row) * N + n0 + a_c4 * 4], true);
            cp16(s2u(&Bs[nb][a_row + 16][a_c4 * 4]),
                 &Bm[(size_t)(kkn + a_row + 16) * N + n0 + a_c4 * 4], true);
            cp_commit();
        }
        int bf = ch & 1;
#pragma unroll
        for (int k = 0; k < 32; k++) {
            float av0 = As[bf][ty][k], av1 = As[bf][ty + 8][k];
            float2 bv = *(const float2*)&Bs[bf][k][tx * 2];
            a00 = fmaf(av0, bv.x, a00); a01 = fmaf(av0, bv.y, a01);
            a10 = fmaf(av1, bv.x, a10); a11 = fmaf(av1, bv.y, a11);
        }
        __syncthreads();
    }

    int r0 = m0 + ty, r1 = m0 + ty + 8;
    int c = n0 + tx * 2;
    float b0 = bias[c], b1 = bias[c + 1];
    if (r0 < M) {
        float2 rr = *(const float2*)&resid[(size_t)r0 * N + c];
        float2 o2 = make_float2(rr.x + a00 + b0, rr.y + a01 + b1);
        *(float2*)&out[(size_t)r0 * N + c] = o2;
    }
    if (r1 < M) {
        float2 rr = *(const float2*)&resid[(size_t)r1 * N + c];
        float2 o2 = make_float2(rr.x + a10 + b0, rr.y + a11 + b1);
        *(float2*)&out[(size_t)r1 * N + c] = o2;
    }
}

// ---------------- head-mean + bias + layernorm: 2 warps/row, 338 blocks -----
__global__ __launch_bounds__(64) void ln_kernel(const float* __restrict__ agg,
                                                const float* __restrict__ bias_l,
                                                const float* __restrict__ g,
                                                const float* __restrict__ bt,
                                                float* __restrict__ out)
{
    int lane = threadIdx.x & 31;
    int wrp = threadIdx.x >> 5;
    int n = blockIdx.x;
    int b = (n >= N_) ? 1 : 0;
    int d = n - b * N_;
    int c = wrp * 128 + lane * 4;

    float4 v = make_float4(0.f, 0.f, 0.f, 0.f);
#pragma unroll
    for (int h = 0; h < H_; h++) {
        float4 t = *(const float4*)&agg[((size_t)(b * H_ + h) * N_ + d) * C_ + c];
        v.x += t.x; v.y += t.y; v.z += t.z; v.w += t.w;
    }
    float4 bb = *(const float4*)&bias_l[c];
    v.x = 0.25f * v.x + bb.x; v.y = 0.25f * v.y + bb.y;
    v.z = 0.25f * v.z + bb.z; v.w = 0.25f * v.w + bb.w;

    __shared__ float red[2][2];
    float s = v.x + v.y + v.z + v.w;
#pragma unroll
    for (int o = 16; o; o >>= 1) s += __shfl_xor_sync(0xffffffffu, s, o);
    if (lane == 0) red[0][wrp] = s;
    __syncthreads();
    float mu = (red[0][0] + red[0][1]) * (1.f / C_);

    float4 e = make_float4(v.x - mu, v.y - mu, v.z - mu, v.w - mu);
    float s2 = e.x * e.x + e.y * e.y + e.z * e.z + e.w * e.w;
#pragma unroll
    for (int o = 16; o; o >>= 1) s2 += __shfl_xor_sync(0xffffffffu, s2, o);
    if (lane == 0) red[1][wrp] = s2;
    __syncthreads();
    float rstd = rsqrtf((red[1][0] + red[1][1]) * (1.f / C_) + 1e-5f);

    float4 gg = *(const float4*)&g[c];
    float4 tb = *(const float4*)&bt[c];
    float4 o4;
    o4.x = e.x * rstd * gg.x + tb.x;
    o4.y = e.y * rstd * gg.y + tb.y;
    o4.z = e.z * rstd * gg.z + tb.z;
    o4.w = e.w * rstd * gg.w + tb.w;
    *(float4*)&out[(size_t)n * C_ + c] = o4;
}

// ---------------- final mean pool per graph ----------------------------------
__global__ void pool_kernel(const float* __restrict__ x, float* __restrict__ out)
{
    int b = blockIdx.x, t = threadIdx.x;
    float s = 0.f;
#pragma unroll 13
    for (int d = 0; d < N_; d++) s += x[(b * N_ + d) * C_ + t];
    out[b * C_ + t] = s * (1.f / N_);
}

// ---------------- host launcher -----------------------------------------------
extern "C" void kernel_launch(void* const* d_in, const int* in_sizes, int n_in,
                              void* d_out, int out_size)
{
    const float* x    = (const float*)d_in[0];
    const float* Wl   = (const float*)d_in[1];
    const float* bl   = (const float*)d_in[2];
    const float* Wr   = (const float*)d_in[3];
    const float* br   = (const float*)d_in[4];
    const float* att  = (const float*)d_in[5];
    const float* bias = (const float*)d_in[6];
    const float* lng  = (const float*)d_in[7];
    const float* lnb  = (const float*)d_in[8];
    const float* W1   = (const float*)d_in[9];
    const float* b1   = (const float*)d_in[10];
    const float* W2   = (const float*)d_in[11];
    const float* b2   = (const float*)d_in[12];

    float *bx, *bxl, *bxr, *bag, *bh, *bm, *bu, *bw;
    cudaGetSymbolAddress((void**)&bx,  g_x);
    cudaGetSymbolAddress((void**)&bxl, g_xl);
    cudaGetSymbolAddress((void**)&bxr, g_xr);
    cudaGetSymbolAddress((void**)&bag, g_agg);
    cudaGetSymbolAddress((void**)&bh,  g_h);
    cudaGetSymbolAddress((void**)&bm,  g_m);
    cudaGetSymbolAddress((void**)&bu,  g_u);
    cudaGetSymbolAddress((void**)&bw,  g_w);

    static int attr_done = 0;
    if (!attr_done) {
        cudaFuncSetAttribute(attn_agg_kernel,
                             cudaFuncAttributeMaxDynamicSharedMemorySize,
                             (int)ATTN_SMEM_BYTES);
        attr_done = 1;
    }

    for (int l = 0; l < L_; l++) {
        const float* xin = (l == 0) ? x : bx;
        gemm_dual<<<dim3(32, 6), 256>>>(xin,
                                        Wl + l * C_ * HC_, bl + l * HC_, bxl,
                                        Wr + l * C_ * HC_, br + l * HC_, bxr,
                                        NN_, C_);
        uw_kernel<<<NN_, 128>>>(bxl, bxr, att + l * H_ * C_, bu, bw);
        attn_agg_kernel<<<dim3(43, 8), 128, ATTN_SMEM_BYTES>>>(
            bxl, bxr, att + l * H_ * C_, bu, bw, bag);
        ln_kernel<<<NN_, 64>>>(bag, bias + l * C_, lng + l * C_, lnb + l * C_, bh);
        gemm_kernel<<<dim3(16, 11), 256>>>(bh, W1 + l * C_ * 2 * C_, b1 + l * 2 * C_,
                                           bm, NN_, 2 * C_, C_);
        gemm16_kernel<<<dim3(8, 22), 128>>>(bm, W2 + l * 2 * C_ * C_, b2 + l * C_,
                                            xin, bx, NN_, C_, 2 * C_);
    }

    pool_kernel<<<B_, 256>>>(bx, (float*)d_out);
}

// round 17
// speedup vs baseline: 1.0288x; 1.0116x over previous
#include <cuda_runtime.h>

#define B_   2
#define N_   169
#define NN_  338
#define C_   256
#define H_   4
#define HC_  1024
#define L_   3

typedef unsigned long long ull;

// ---------------- scratch (device globals) ---------------------------------
__device__ float g_x[NN_ * C_];               // running node features
__device__ float g_xl[NN_ * HC_];             // x @ Wl + bl
__device__ float g_xr[NN_ * HC_];             // x @ Wr + br
__device__ float g_agg[B_ * H_ * N_ * C_];    // per-head aggregation partials
__device__ float g_h[NN_ * C_];               // post layernorm
__device__ float g_m[NN_ * 2 * C_];           // mlp hidden
__device__ float g_u[H_ * NN_];               // <att, xl_n> per head
__device__ float g_w[H_ * NN_];               // <att, xr_n> per head

// ---------------- cp.async helpers ------------------------------------------
__device__ __forceinline__ unsigned s2u(const void* p)
{
    return (unsigned)__cvta_generic_to_shared(p);
}
__device__ __forceinline__ void cp16(unsigned dst, const void* src, bool ok)
{
    int sz = ok ? 16 : 0;
    asm volatile("cp.async.cg.shared.global [%0], [%1], 16, %2;"
                 :: "r"(dst), "l"(src), "r"(sz));
}
__device__ __forceinline__ void cp_commit()
{
    asm volatile("cp.async.commit_group;");
}
__device__ __forceinline__ void cp_wait0()
{
    asm volatile("cp.async.wait_group 0;" ::: "memory");
}

// ---------------- u/w rank-1 terms: u[h,n]=<att_h, xl[n,h,:]>, w likewise ---
__global__ __launch_bounds__(128) void uw_kernel(const float* __restrict__ xl,
                                                 const float* __restrict__ xr,
                                                 const float* __restrict__ att_l,
                                                 float* __restrict__ u,
                                                 float* __restrict__ w)
{
    int n = blockIdx.x;
    int h = threadIdx.x >> 5, lane = threadIdx.x & 31;
    const float4* xlp = (const float4*)&xl[(size_t)n * HC_ + h * C_];
    const float4* xrp = (const float4*)&xr[(size_t)n * HC_ + h * C_];
    const float4* ap  = (const float4*)&att_l[h * C_];
    float su = 0.f, sw = 0.f;
#pragma unroll
    for (int i = 0; i < 2; i++) {
        float4 a = ap[lane + 32 * i];
        float4 vl = xlp[lane + 32 * i];
        float4 vr = xrp[lane + 32 * i];
        su += a.x * vl.x + a.y * vl.y + a.z * vl.z + a.w * vl.w;
        sw += a.x * vr.x + a.y * vr.y + a.z * vr.z + a.w * vr.w;
    }
#pragma unroll
    for (int o = 16; o; o >>= 1) {
        su += __shfl_xor_sync(0xffffffffu, su, o);
        sw += __shfl_xor_sync(0xffffffffu, sw, o);
    }
    if (lane == 0) {
        u[h * NN_ + n] = su;
        w[h * NN_ + n] = sw;
    }
}

// ---------------- fused logits + softmax + aggregation ----------------------
// grid (43 d-tiles, 8 bh), block 128 = 4 warps. (R14 proven config)
struct AttnSmem {
    union {
        struct {
            float XLs[2][6][32][36];
            float XR[4][256];
            float A4[256];
        } pa;
        struct {
            float Xs[2][32][260];
        } pb;
    } u;
    float AL[4][193];
    float MX[4][2];
    float SS[4][2];
};
#define ATTN_SMEM_BYTES sizeof(AttnSmem)

__global__ __launch_bounds__(128) void attn_agg_kernel(const float* __restrict__ xl,
                                                       const float* __restrict__ xr,
                                                       const float* __restrict__ att_l,
                                                       const float* __restrict__ u,
                                                       const float* __restrict__ w,
                                                       float* __restrict__ agg)
{
    extern __shared__ __align__(16) char smem_raw[];
    AttnSmem* sm = (AttnSmem*)smem_raw;

    int tid = threadIdx.x;
    int lane = tid & 31;
    int wid = tid >> 5;
    int ty = wid >> 1;            // d-pair 0..1
    int hf = wid & 1;             // s-half: bands {0,1,2} or {3,4,5}
    int dt = blockIdx.x, bh = blockIdx.y;
    int b = bh >> 2, h = bh & 3;
    int d0 = dt * 4 + ty * 2;
    int d1 = d0 + 1;
    bool dok0 = d0 < N_, dok1 = d1 < N_;

    const float* xlh = xl + (size_t)b * N_ * HC_ + h * C_;

    // ---- stage chunk 0 of XLs (cp16), then XR + A4 (sync LDG, once) ----
#pragma unroll
    for (int i = 0; i < 12; i++) {
        int f = tid + 128 * i;          // 1536 float4 total
        int st = f >> 8;
        int rem = f & 255;
        int row = rem >> 3;
        int c4 = rem & 7;
        int s = st * 32 + row;
        bool ok = s < N_;
        cp16(s2u(&sm->u.pa.XLs[0][st][row][c4 * 4]),
             &xlh[(size_t)(ok ? s : 0) * HC_ + c4 * 4], ok);
    }
    cp_commit();
#pragma unroll
    for (int i = 0; i < 4; i++) {
        int f = tid + 128 * i;          // 512 float2 for XR[4][256]
        int row = f >> 7;
        int cc = (f & 127) * 2;
        int dr = dt * 4 + row;
        float2 v = make_float2(0.f, 0.f);
        if (dr < N_) v = *(const float2*)&xr[(size_t)(b * N_ + dr) * HC_ + h * C_ + cc];
        *(float2*)&sm->u.pa.XR[row][cc] = v;
    }
    {
        float2 a = *(const float2*)&att_l[h * C_ + tid * 2];
        sm->u.pa.A4[tid * 2]     = 0.4f * a.x;
        sm->u.pa.A4[tid * 2 + 1] = 0.4f * a.y;
    }

    ull acc0[3], acc1[3];
#pragma unroll
    for (int j = 0; j < 3; j++) { acc0[j] = 0ull; acc1[j] = 0ull; }
    const ull msk = 0x7FFFFFFF7FFFFFFFULL;

    // ---------------- Phase A: pipelined over 8 ck-chunks ----------------
#pragma unroll 1
    for (int ch = 0; ch < 8; ch++) {
        cp_wait0();
        __syncthreads();
        if (ch + 1 < 8) {
            int nb = (ch + 1) & 1;
            int ckn = (ch + 1) * 32;
#pragma unroll
            for (int i = 0; i < 12; i++) {
                int f = tid + 128 * i;
                int st = f >> 8;
                int rem = f & 255;
                int row = rem >> 3;
                int c4 = rem & 7;
                int s = st * 32 + row;
                bool ok = s < N_;
                cp16(s2u(&sm->u.pa.XLs[nb][st][row][c4 * 4]),
                     &xlh[(size_t)(ok ? s : 0) * HC_ + ckn + c4 * 4], ok);
            }
            cp_commit();
        }
        int bf = ch & 1;
        int ck = ch * 32;
#pragma unroll
        for (int c4 = 0; c4 < 8; c4++) {
            ulonglong2 r0 = *(const ulonglong2*)&sm->u.pa.XR[ty * 2][ck + c4 * 4];
            ulonglong2 r1 = *(const ulonglong2*)&sm->u.pa.XR[ty * 2 + 1][ck + c4 * 4];
            ulonglong2 a4 = *(const ulonglong2*)&sm->u.pa.A4[ck + c4 * 4];
#pragma unroll
            for (int j = 0; j < 3; j++) {
                ulonglong2 l = *(const ulonglong2*)&sm->u.pa.XLs[bf][hf * 3 + j][lane][c4 * 4];
                ull s, m;
                asm("add.rn.f32x2 %0, %1, %2;" : "=l"(s) : "l"(l.x), "l"(r0.x));
                asm("and.b64 %0, %1, %2;"      : "=l"(m) : "l"(s), "l"(msk));
                asm("fma.rn.f32x2 %0, %1, %2, %0;" : "+l"(acc0[j]) : "l"(m), "l"(a4.x));
                asm("add.rn.f32x2 %0, %1, %2;" : "=l"(s) : "l"(l.y), "l"(r0.y));
                asm("and.b64 %0, %1, %2;"      : "=l"(m) : "l"(s), "l"(msk));
                asm("fma.rn.f32x2 %0, %1, %2, %0;" : "+l"(acc0[j]) : "l"(m), "l"(a4.y));
                asm("add.rn.f32x2 %0, %1, %2;" : "=l"(s) : "l"(l.x), "l"(r1.x));
                asm("and.b64 %0, %1, %2;"      : "=l"(m) : "l"(s), "l"(msk));
                asm("fma.rn.f32x2 %0, %1, %2, %0;" : "+l"(acc1[j]) : "l"(m), "l"(a4.x));
                asm("add.rn.f32x2 %0, %1, %2;" : "=l"(s) : "l"(l.y), "l"(r1.y));
                asm("and.b64 %0, %1, %2;"      : "=l"(m) : "l"(s), "l"(msk));
                asm("fma.rn.f32x2 %0, %1, %2, %0;" : "+l"(acc1[j]) : "l"(m), "l"(a4.y));
            }
        }
        __syncthreads();
    }

    // ---- prefetch phase-B chunk 0 now; softmax hides its latency ----
#pragma unroll
    for (int i = 0; i < 16; i++) {
        int f = tid + 128 * i;          // 2048 float4
        int row = f >> 6, col4 = f & 63;
        int s = row;
        bool ok = s < N_;
        cp16(s2u(&sm->u.pb.Xs[0][row][col4 * 4]),
             &xlh[(size_t)(ok ? s : 0) * HC_ + col4 * 4], ok);
    }
    cp_commit();

    // ---------------- softmax (2 d-rows per warp, 2-warp combine) --------
    float w_d0 = dok0 ? w[h * NN_ + b * N_ + d0] : 0.f;
    float w_d1 = dok1 ? w[h * NN_ + b * N_ + d1] : 0.f;
    float lg0[3], lg1[3];
    float mx0 = -1e30f, mx1 = -1e30f;
#pragma unroll
    for (int j = 0; j < 3; j++) {
        int s = (hf * 3 + j) * 32 + lane;
        float uv = (s < N_) ? u[h * NN_ + b * N_ + s] : 0.f;
        {
            ull a = acc0[j];
            float lo = __uint_as_float((unsigned)(a & 0xffffffffu));
            float hi = __uint_as_float((unsigned)(a >> 32));
            float v = 0.6f * (uv + w_d0) + lo + hi;
            if (s >= N_ || s == d0) v = -1e30f;
            lg0[j] = v;
            mx0 = fmaxf(mx0, v);
        }
        {
            ull a = acc1[j];
            float lo = __uint_as_float((unsigned)(a & 0xffffffffu));
            float hi = __uint_as_float((unsigned)(a >> 32));
            float v = 0.6f * (uv + w_d1) + lo + hi;
            if (s >= N_ || s == d1) v = -1e30f;
            lg1[j] = v;
            mx1 = fmaxf(mx1, v);
        }
    }
#pragma unroll
    for (int o = 16; o; o >>= 1) {
        mx0 = fmaxf(mx0, __shfl_xor_sync(0xffffffffu, mx0, o));
        mx1 = fmaxf(mx1, __shfl_xor_sync(0xffffffffu, mx1, o));
    }
    if (lane == 0) {
        sm->MX[ty * 2][hf]     = mx0;
        sm->MX[ty * 2 + 1][hf] = mx1;
    }
    __syncthreads();
    float gmx0 = fmaxf(sm->MX[ty * 2][0],     sm->MX[ty * 2][1]);
    float gmx1 = fmaxf(sm->MX[ty * 2 + 1][0], sm->MX[ty * 2 + 1][1]);
    float sum0 = 0.f, sum1 = 0.f;
#pragma unroll
    for (int j = 0; j < 3; j++) {
        float e0 = __expf(lg0[j] - gmx0);
        float e1 = __expf(lg1[j] - gmx1);
        lg0[j] = e0; lg1[j] = e1;
        sum0 += e0; sum1 += e1;
    }
#pragma unroll
    for (int o = 16; o; o >>= 1) {
        sum0 += __shfl_xor_sync(0xffffffffu, sum0, o);
        sum1 += __shfl_xor_sync(0xffffffffu, sum1, o);
    }
    if (lane == 0) {
        sm->SS[ty * 2][hf]     = sum0;
        sm->SS[ty * 2 + 1][hf] = sum1;
    }
    __syncthreads();
    float inv0 = 1.f / (sm->SS[ty * 2][0]     + sm->SS[ty * 2][1]     + 1e-16f);
    float inv1 = 1.f / (sm->SS[ty * 2 + 1][0] + sm->SS[ty * 2 + 1][1] + 1e-16f);
#pragma unroll
    for (int j = 0; j < 3; j++) {
        sm->AL[ty * 2][(hf * 3 + j) * 32 + lane]     = lg0[j] * inv0;
        sm->AL[ty * 2 + 1][(hf * 3 + j) * 32 + lane] = lg1[j] * inv1;
    }
    // AL write -> read ordering provided by the __syncthreads at phase-B loop head

    // ---------------- Phase B: warp = (d-pair, c-half) -------------------
    float4 accA = make_float4(0.f, 0.f, 0.f, 0.f);   // d0
    float4 accB = make_float4(0.f, 0.f, 0.f, 0.f);   // d1
    int cb = hf * 128 + lane * 4;
#pragma unroll 1
    for (int ch = 0; ch < 6; ch++) {
        cp_wait0();
        __syncthreads();
        if (ch + 1 < 6) {
            int nb = (ch + 1) & 1;
            int skn = (ch + 1) * 32;
#pragma unroll
            for (int i = 0; i < 16; i++) {
                int f = tid + 128 * i;
                int row = f >> 6, col4 = f & 63;
                int s = skn + row;
                bool ok = s < N_;
                cp16(s2u(&sm->u.pb.Xs[nb][row][col4 * 4]),
                     &xlh[(size_t)(ok ? s : 0) * HC_ + col4 * 4], ok);
            }
            cp_commit();
        }
        int bf = ch & 1;
        int sk = ch * 32;
#pragma unroll
        for (int k = 0; k < 32; k++) {
            float av0 = sm->AL[ty * 2][sk + k];
            float av1 = sm->AL[ty * 2 + 1][sk + k];
            float4 x = *(const float4*)&sm->u.pb.Xs[bf][k][cb];
            accA.x = fmaf(av0, x.x, accA.x); accA.y = fmaf(av0, x.y, accA.y);
            accA.z = fmaf(av0, x.z, accA.z); accA.w = fmaf(av0, x.w, accA.w);
            accB.x = fmaf(av1, x.x, accB.x); accB.y = fmaf(av1, x.y, accB.y);
            accB.z = fmaf(av1, x.z, accB.z); accB.w = fmaf(av1, x.w, accB.w);
        }
        __syncthreads();
    }

    if (dok0)
        *(float4*)&agg[((size_t)bh * N_ + d0) * C_ + cb] = accA;
    if (dok1)
        *(float4*)&agg[((size_t)bh * N_ + d1) * C_ + cb] = accB;
}

// ---------------- fused xl/xr GEMM: 64x64 tile, 4x4/thread, cp.async --------
__global__ __launch_bounds__(256) void gemm_dual(const float* __restrict__ A,
                                                 const float* __restrict__ B1,
                                                 const float* __restrict__ c1,
                                                 float* __restrict__ o1,
                                                 const float* __restrict__ B2,
                                                 const float* __restrict__ c2p,
                                                 float* __restrict__ o2,
                                                 int M, int K)
{
    __shared__ __align__(16) float As[2][64][36];
    __shared__ __align__(16) float Bs[2][32][68];

    const float* Bm;
    const float* bias;
    float* out;
    int n0;
    if (blockIdx.x < 16) { Bm = B1; bias = c1;  out = o1; n0 = blockIdx.x * 64; }
    else                 { Bm = B2; bias = c2p; out = o2; n0 = (blockIdx.x - 16) * 64; }

    int tid = threadIdx.x;
    int tx = tid & 15, ty = tid >> 4;
    int m0 = blockIdx.y * 64;

    int a_row = tid >> 2, a_c4a = (tid & 3) * 2;
    int b_row0 = tid >> 4, b_c4 = tid & 15;

    {
        bool okA = (m0 + a_row) < M;
        const float* srcA = &A[(size_t)(m0 + (okA ? a_row : 0)) * K + a_c4a * 4];
        cp16(s2u(&As[0][a_row][a_c4a * 4]), srcA, okA);
        cp16(s2u(&As[0][a_row][(a_c4a + 1) * 4]), srcA + 4, okA);
        cp16(s2u(&Bs[0][b_row0][b_c4 * 4]),
             &Bm[(size_t)b_row0 * HC_ + n0 + b_c4 * 4], true);
        cp16(s2u(&Bs[0][b_row0 + 16][b_c4 * 4]),
             &Bm[(size_t)(b_row0 + 16) * HC_ + n0 + b_c4 * 4], true);
    }
    cp_commit();

    float acc[4][4];
#pragma unroll
    for (int i = 0; i < 4; i++)
#pragma unroll
        for (int j = 0; j < 4; j++) acc[i][j] = 0.f;

    int nch = K / 32;
#pragma unroll 1
    for (int ch = 0; ch < nch; ch++) {
        cp_wait0();
        __syncthreads();
        if (ch + 1 < nch) {
            int nb = (ch + 1) & 1;
            int kkn = (ch + 1) * 32;
            bool okA = (m0 + a_row) < M;
            const float* srcA = &A[(size_t)(m0 + (okA ? a_row : 0)) * K + kkn + a_c4a * 4];
            cp16(s2u(&As[nb][a_row][a_c4a * 4]), srcA, okA);
            cp16(s2u(&As[nb][a_row][(a_c4a + 1) * 4]), srcA + 4, okA);
            cp16(s2u(&Bs[nb][b_row0][b_c4 * 4]),
                 &Bm[(size_t)(kkn + b_row0) * HC_ + n0 + b_c4 * 4], true);
            cp16(s2u(&Bs[nb][b_row0 + 16][b_c4 * 4]),
                 &Bm[(size_t)(kkn + b_row0 + 16) * HC_ + n0 + b_c4 * 4], true);
            cp_commit();
        }
        int bf = ch & 1;
#pragma unroll
        for (int k = 0; k < 32; k++) {
            float a0 = As[bf][ty * 4 + 0][k];
            float a1 = As[bf][ty * 4 + 1][k];
            float a2 = As[bf][ty * 4 + 2][k];
            float a3 = As[bf][ty * 4 + 3][k];
            float4 bv = *(const float4*)&Bs[bf][k][tx * 4];
            acc[0][0] = fmaf(a0, bv.x, acc[0][0]); acc[0][1] = fmaf(a0, bv.y, acc[0][1]);
            acc[0][2] = fmaf(a0, bv.z, acc[0][2]); acc[0][3] = fmaf(a0, bv.w, acc[0][3]);
            acc[1][0] = fmaf(a1, bv.x, acc[1][0]); acc[1][1] = fmaf(a1, bv.y, acc[1][1]);
            acc[1][2] = fmaf(a1, bv.z, acc[1][2]); acc[1][3] = fmaf(a1, bv.w, acc[1][3]);
            acc[2][0] = fmaf(a2, bv.x, acc[2][0]); acc[2][1] = fmaf(a2, bv.y, acc[2][1]);
            acc[2][2] = fmaf(a2, bv.z, acc[2][2]); acc[2][3] = fmaf(a2, bv.w, acc[2][3]);
            acc[3][0] = fmaf(a3, bv.x, acc[3][0]); acc[3][1] = fmaf(a3, bv.y, acc[3][1]);
            acc[3][2] = fmaf(a3, bv.z, acc[3][2]); acc[3][3] = fmaf(a3, bv.w, acc[3][3]);
        }
        __syncthreads();
    }

    float4 bb = *(const float4*)&bias[n0 + tx * 4];
#pragma unroll
    for (int i = 0; i < 4; i++) {
        int r = m0 + ty * 4 + i;
        if (r < M) {
            float4 o4;
            o4.x = acc[i][0] + bb.x;
            o4.y = acc[i][1] + bb.y;
            o4.z = acc[i][2] + bb.z;
            o4.w = acc[i][3] + bb.w;
            *(float4*)&out[(size_t)r * HC_ + n0 + tx * 4] = o4;
        }
    }
}

// ---------------- generic 32x32 GEMM, cp.async (MLP1: relu) -----------------
__global__ void gemm_kernel(const float* __restrict__ A,
                            const float* __restrict__ Bm,
                            const float* __restrict__ bias,
                            float* __restrict__ out,
                            int M, int N, int K)
{
    __shared__ __align__(16) float As[2][32][36];
    __shared__ __align__(16) float Bs[2][32][36];
    int tid = threadIdx.x;
    int tx = tid & 15, ty = tid >> 4;
    int m0 = blockIdx.y * 32;
    int n0 = blockIdx.x * 32;
    int lr = tid >> 3, lc4 = tid & 7;
    float a00 = 0.f, a01 = 0.f, a10 = 0.f, a11 = 0.f;

    {
        bool okA = (m0 + lr) < M;
        cp16(s2u(&As[0][lr][lc4 * 4]),
             &A[(size_t)(m0 + (okA ? lr : 0)) * K + lc4 * 4], okA);
        cp16(s2u(&Bs[0][lr][lc4 * 4]),
             &Bm[(size_t)lr * N + n0 + lc4 * 4], true);
    }
    cp_commit();

    int nch = K / 32;
#pragma unroll 1
    for (int ch = 0; ch < nch; ch++) {
        cp_wait0();
        __syncthreads();
        if (ch + 1 < nch) {
            int nb = (ch + 1) & 1;
            int kkn = (ch + 1) * 32;
            bool okA = (m0 + lr) < M;
            cp16(s2u(&As[nb][lr][lc4 * 4]),
                 &A[(size_t)(m0 + (okA ? lr : 0)) * K + kkn + lc4 * 4], okA);
            cp16(s2u(&Bs[nb][lr][lc4 * 4]),
                 &Bm[(size_t)(kkn + lr) * N + n0 + lc4 * 4], true);
            cp_commit();
        }
        int bf = ch & 1;
#pragma unroll
        for (int k = 0; k < 32; k++) {
            float av0 = As[bf][ty][k],      av1 = As[bf][ty + 16][k];
            float bv0 = Bs[bf][k][tx],      bv1 = Bs[bf][k][tx + 16];
            a00 = fmaf(av0, bv0, a00);  a01 = fmaf(av0, bv1, a01);
            a10 = fmaf(av1, bv0, a10);  a11 = fmaf(av1, bv1, a11);
        }
        __syncthreads();
    }

    int r0 = m0 + ty, r1 = m0 + ty + 16;
    int c0 = n0 + tx, c1 = n0 + tx + 16;
    float b0 = bias[c0], b1 = bias[c1];
    if (r0 < M) { out[r0 * N + c0] = fmaxf(a00 + b0, 0.f); out[r0 * N + c1] = fmaxf(a01 + b1, 0.f); }
    if (r1 < M) { out[r1 * N + c0] = fmaxf(a10 + b0, 0.f); out[r1 * N + c1] = fmaxf(a11 + b1, 0.f); }
}

// ---------------- 16x32-tile GEMM, 128 threads (MLP2: residual) -------------
// grid (N/32, ceil(M/16)) -> 176 blocks for M=338,N=256: full-chip spread.
__global__ __launch_bounds__(128) void gemm16_kernel(const float* __restrict__ A,
                                                     const float* __restrict__ Bm,
                                                     const float* __restrict__ bias,
                                                     const float* __restrict__ resid,
                                                     float* __restrict__ out,
                                                     int M, int N, int K)
{
    __shared__ __align__(16) float As[2][16][36];
    __shared__ __align__(16) float Bs[2][32][36];
    int tid = threadIdx.x;
    int tx = tid & 15, ty = tid >> 4;        // ty 0..7
    int m0 = blockIdx.y * 16;
    int n0 = blockIdx.x * 32;
    int a_row = tid >> 3, a_c4 = tid & 7;    // 16 rows x 8 c4 = 128
    float a00 = 0.f, a01 = 0.f, a10 = 0.f, a11 = 0.f;

    {
        bool okA = (m0 + a_row) < M;
        cp16(s2u(&As[0][a_row][a_c4 * 4]),
             &A[(size_t)(m0 + (okA ? a_row : 0)) * K + a_c4 * 4], okA);
        cp16(s2u(&Bs[0][a_row][a_c4 * 4]),
             &Bm[(size_t)a_row * N + n0 + a_c4 * 4], true);
        cp16(s2u(&Bs[0][a_row + 16][a_c4 * 4]),
             &Bm[(size_t)(a_row + 16) * N + n0 + a_c4 * 4], true);
    }
    cp_commit();

    int nch = K / 32;
#pragma unroll 1
    for (int ch = 0; ch < nch; ch++) {
        cp_wait0();
        __syncthreads();
        if (ch + 1 < nch) {
            int nb = (ch + 1) & 1;
            int kkn = (ch + 1) * 32;
            bool okA = (m0 + a_row) < M;
            cp16(s2u(&As[nb][a_row][a_c4 * 4]),
                 &A[(size_t)(m0 + (okA ? a_row : 0)) * K + kkn + a_c4 * 4], okA);
            cp16(s2u(&Bs[nb][a_row][a_c4 * 4]),
                 &Bm[(size_t)(kkn + a_row) * N + n0 + a_c4 * 4], true);
            cp16(s2u(&Bs[nb][a_row + 16][a_c4 * 4]),
                 &Bm[(size_t)(kkn + a_row + 16) * N + n0 + a_c4 * 4], true);
            cp_commit();
        }
        int bf = ch & 1;
#pragma unroll
        for (int k = 0; k < 32; k++) {
            float av0 = As[bf][ty][k], av1 = As[bf][ty + 8][k];
            float2 bv = *(const float2*)&Bs[bf][k][tx * 2];
            a00 = fmaf(av0, bv.x, a00); a01 = fmaf(av0, bv.y, a01);
            a10 = fmaf(av1, bv.x, a10); a11 = fmaf(av1, bv.y, a11);
        }
        __syncthreads();
    }

    int r0 = m0 + ty, r1 = m0 + ty + 8;
    int c = n0 + tx * 2;
    float b0 = bias[c], b1 = bias[c + 1];
    if (r0 < M) {
        float2 rr = *(const float2*)&resid[(size_t)r0 * N + c];
        float2 o2 = make_float2(rr.x + a00 + b0, rr.y + a01 + b1);
        *(float2*)&out[(size_t)r0 * N + c] = o2;
    }
    if (r1 < M) {
        float2 rr = *(const float2*)&resid[(size_t)r1 * N + c];
        float2 o2 = make_float2(rr.x + a10 + b0, rr.y + a11 + b1);
        *(float2*)&out[(size_t)r1 * N + c] = o2;
    }
}

// ---------------- head-mean + bias + layernorm: 2 warps/row, 338 blocks -----
__global__ __launch_bounds__(64) void ln_kernel(const float* __restrict__ agg,
                                                const float* __restrict__ bias_l,
                                                const float* __restrict__ g,
                                                const float* __restrict__ bt,
                                                float* __restrict__ out)
{
    int lane = threadIdx.x & 31;
    int wrp = threadIdx.x >> 5;
    int n = blockIdx.x;
    int b = (n >= N_) ? 1 : 0;
    int d = n - b * N_;
    int c = wrp * 128 + lane * 4;

    float4 v = make_float4(0.f, 0.f, 0.f, 0.f);
#pragma unroll
    for (int h = 0; h < H_; h++) {
        float4 t = *(const float4*)&agg[((size_t)(b * H_ + h) * N_ + d) * C_ + c];
        v.x += t.x; v.y += t.y; v.z += t.z; v.w += t.w;
    }
    float4 bb = *(const float4*)&bias_l[c];
    v.x = 0.25f * v.x + bb.x; v.y = 0.25f * v.y + bb.y;
    v.z = 0.25f * v.z + bb.z; v.w = 0.25f * v.w + bb.w;

    __shared__ float red[2][2];
    float s = v.x + v.y + v.z + v.w;
#pragma unroll
    for (int o = 16; o; o >>= 1) s += __shfl_xor_sync(0xffffffffu, s, o);
    if (lane == 0) red[0][wrp] = s;
    __syncthreads();
    float mu = (red[0][0] + red[0][1]) * (1.f / C_);

    float4 e = make_float4(v.x - mu, v.y - mu, v.z - mu, v.w - mu);
    float s2 = e.x * e.x + e.y * e.y + e.z * e.z + e.w * e.w;
#pragma unroll
    for (int o = 16; o; o >>= 1) s2 += __shfl_xor_sync(0xffffffffu, s2, o);
    if (lane == 0) red[1][wrp] = s2;
    __syncthreads();
    float rstd = rsqrtf((red[1][0] + red[1][1]) * (1.f / C_) + 1e-5f);

    float4 gg = *(const float4*)&g[c];
    float4 tb = *(const float4*)&bt[c];
    float4 o4;
    o4.x = e.x * rstd * gg.x + tb.x;
    o4.y = e.y * rstd * gg.y + tb.y;
    o4.z = e.z * rstd * gg.z + tb.z;
    o4.w = e.w * rstd * gg.w + tb.w;
    *(float4*)&out[(size_t)n * C_ + c] = o4;
}

// ---------------- final mean pool per graph ----------------------------------
__global__ void pool_kernel(const float* __restrict__ x, float* __restrict__ out)
{
    int b = blockIdx.x, t = threadIdx.x;
    float s = 0.f;
#pragma unroll 13
    for (int d = 0; d < N_; d++) s += x[(b * N_ + d) * C_ + t];
    out[b * C_ + t] = s * (1.f / N_);
}

// ---------------- host launcher -----------------------------------------------
extern "C" void kernel_launch(void* const* d_in, const int* in_sizes, int n_in,
                              void* d_out, int out_size)
{
    const float* x    = (const float*)d_in[0];
    const float* Wl   = (const float*)d_in[1];
    const float* bl   = (const float*)d_in[2];
    const float* Wr   = (const float*)d_in[3];
    const float* br   = (const float*)d_in[4];
    const float* att  = (const float*)d_in[5];
    const float* bias = (const float*)d_in[6];
    const float* lng  = (const float*)d_in[7];
    const float* lnb  = (const float*)d_in[8];
    const float* W1   = (const float*)d_in[9];
    const float* b1   = (const float*)d_in[10];
    const float* W2   = (const float*)d_in[11];
    const float* b2   = (const float*)d_in[12];

    float *bx, *bxl, *bxr, *bag, *bh, *bm, *bu, *bw;
    cudaGetSymbolAddress((void**)&bx,  g_x);
    cudaGetSymbolAddress((void**)&bxl, g_xl);
    cudaGetSymbolAddress((void**)&bxr, g_xr);
    cudaGetSymbolAddress((void**)&bag, g_agg);
    cudaGetSymbolAddress((void**)&bh,  g_h);
    cudaGetSymbolAddress((void**)&bm,  g_m);
    cudaGetSymbolAddress((void**)&bu,  g_u);
    cudaGetSymbolAddress((void**)&bw,  g_w);

    static int attr_done = 0;
    if (!attr_done) {
        cudaFuncSetAttribute(attn_agg_kernel,
                             cudaFuncAttributeMaxDynamicSharedMemorySize,
                             (int)ATTN_SMEM_BYTES);
        attr_done = 1;
    }

    for (int l = 0; l < L_; l++) {
        const float* xin = (l == 0) ? x : bx;
        gemm_dual<<<dim3(32, 6), 256>>>(xin,
                                        Wl + l * C_ * HC_, bl + l * HC_, bxl,
                                        Wr + l * C_ * HC_, br + l * HC_, bxr,
                                        NN_, C_);
        uw_kernel<<<NN_, 128>>>(bxl, bxr, att + l * H_ * C_, bu, bw);
        attn_agg_kernel<<<dim3(43, 8), 128, ATTN_SMEM_BYTES>>>(
            bxl, bxr, att + l * H_ * C_, bu, bw, bag);
        ln_kernel<<<NN_, 64>>>(bag, bias + l * C_, lng + l * C_, lnb + l * C_, bh);
        gemm_kernel<<<dim3(16, 11), 256>>>(bh, W1 + l * C_ * 2 * C_, b1 + l * 2 * C_,
                                           bm, NN_, 2 * C_, C_);
        gemm16_kernel<<<dim3(8, 22), 128>>>(bm, W2 + l * 2 * C_ * C_, b2 + l * C_,
                                            xin, bx, NN_, C_, 2 * C_);
    }

    pool_kernel<<<B_, 256>>>(bx, (float*)d_out);
}